// round 1
// baseline (speedup 1.0000x reference)
#include <cuda_runtime.h>
#include <cuda_bf16.h>

#define N_TASKS   8
#define D_MODEL   1024
#define HIDDEN    1024
#define N_CLASSES 100
#define BATCH     8192

// ---------------- device scratch (no allocations allowed) ----------------
__device__ int   g_counts[N_TASKS];
__device__ int   g_rowids[N_TASKS * BATCH];
__device__ float g_h[(size_t)BATCH * HIDDEN];   // 32 MB hidden activations

// ---------------- bucketing ----------------
__global__ void zero_counts_kernel() {
    if (threadIdx.x < N_TASKS) g_counts[threadIdx.x] = 0;
}

__global__ void bucket_rows_kernel(const int* __restrict__ task_id) {
    int b = blockIdx.x * blockDim.x + threadIdx.x;
    if (b < BATCH) {
        int t = task_id[b];
        int pos = atomicAdd(&g_counts[t], 1);
        g_rowids[t * BATCH + pos] = b;
    }
}

// ---------------- layer 1: h = relu(x @ W1[t] + b1[t]) ----------------
// Tile: BM=128, BN=128, BK=8; 256 threads; each thread computes 8x8.
__global__ __launch_bounds__(256, 2)
void layer1_kernel(const float* __restrict__ x,
                   const float* __restrict__ W1,
                   const float* __restrict__ b1) {
    const int t   = blockIdx.z;
    const int cnt = g_counts[t];
    const int m0  = blockIdx.y * 128;
    if (m0 >= cnt) return;
    const int n0  = blockIdx.x * 128;

    const int* rows = &g_rowids[t * BATCH];
    const float* W  = W1 + (size_t)t * D_MODEL * HIDDEN;

    __shared__ float As[8][132];   // [k][m], padded
    __shared__ float Bs[8][132];   // [k][n], padded
    __shared__ int   rowid_s[128];

    const int tid = threadIdx.x;
    if (tid < 128) {
        int m = m0 + tid;
        rowid_s[tid] = (m < cnt) ? rows[m] : -1;
    }
    __syncthreads();

    // A loader mapping: 128 rows x 8 k = 256 float4
    const int a_row = tid >> 1;
    const int a_k   = (tid & 1) * 4;
    // B loader mapping: 8 k x 128 n = 256 float4
    const int b_k   = tid >> 5;
    const int b_n   = (tid & 31) * 4;

    const int ty = tid >> 4;      // 0..15 -> rows ty*8..ty*8+7
    const int tx = tid & 15;      // 0..15 -> cols tx*8..tx*8+7

    float acc[8][8];
    #pragma unroll
    for (int i = 0; i < 8; i++)
        #pragma unroll
        for (int j = 0; j < 8; j++) acc[i][j] = 0.f;

    const int a_r = rowid_s[a_row];
    const float* a_src = (a_r >= 0) ? &x[(size_t)a_r * D_MODEL + a_k] : nullptr;

    for (int k0 = 0; k0 < D_MODEL; k0 += 8) {
        float4 av = make_float4(0.f, 0.f, 0.f, 0.f);
        if (a_src) av = *reinterpret_cast<const float4*>(a_src + k0);
        As[a_k + 0][a_row] = av.x;
        As[a_k + 1][a_row] = av.y;
        As[a_k + 2][a_row] = av.z;
        As[a_k + 3][a_row] = av.w;

        float4 bv = *reinterpret_cast<const float4*>(
            &W[(size_t)(k0 + b_k) * HIDDEN + n0 + b_n]);
        *reinterpret_cast<float4*>(&Bs[b_k][b_n]) = bv;
        __syncthreads();

        #pragma unroll
        for (int k = 0; k < 8; k++) {
            float4 a0 = *reinterpret_cast<const float4*>(&As[k][ty * 8]);
            float4 a1 = *reinterpret_cast<const float4*>(&As[k][ty * 8 + 4]);
            float4 c0 = *reinterpret_cast<const float4*>(&Bs[k][tx * 8]);
            float4 c1 = *reinterpret_cast<const float4*>(&Bs[k][tx * 8 + 4]);
            float a[8] = {a0.x, a0.y, a0.z, a0.w, a1.x, a1.y, a1.z, a1.w};
            float b[8] = {c0.x, c0.y, c0.z, c0.w, c1.x, c1.y, c1.z, c1.w};
            #pragma unroll
            for (int i = 0; i < 8; i++)
                #pragma unroll
                for (int j = 0; j < 8; j++)
                    acc[i][j] = fmaf(a[i], b[j], acc[i][j]);
        }
        __syncthreads();
    }

    // epilogue: bias + relu, scatter to g_h at original row index
    float bias[8];
    #pragma unroll
    for (int j = 0; j < 8; j++)
        bias[j] = b1[t * HIDDEN + n0 + tx * 8 + j];

    #pragma unroll
    for (int i = 0; i < 8; i++) {
        int r = rowid_s[ty * 8 + i];
        if (r < 0) continue;
        float v[8];
        #pragma unroll
        for (int j = 0; j < 8; j++) {
            float s = acc[i][j] + bias[j];
            v[j] = s > 0.f ? s : 0.f;
        }
        float* dst = &g_h[(size_t)r * HIDDEN + n0 + tx * 8];
        *reinterpret_cast<float4*>(dst)     = make_float4(v[0], v[1], v[2], v[3]);
        *reinterpret_cast<float4*>(dst + 4) = make_float4(v[4], v[5], v[6], v[7]);
    }
}

// ---------------- layer 2: out = h @ W2[t] + b2[t] ----------------
// Tile: BM=64, BN=112 (covers N=100), BK=8; 256 threads; each thread 4x7.
__global__ __launch_bounds__(256, 2)
void layer2_kernel(const float* __restrict__ W2,
                   const float* __restrict__ b2,
                   float* __restrict__ out) {
    const int t   = blockIdx.z;
    const int cnt = g_counts[t];
    const int m0  = blockIdx.y * 64;
    if (m0 >= cnt) return;

    const int* rows = &g_rowids[t * BATCH];
    const float* W  = W2 + (size_t)t * HIDDEN * N_CLASSES;

    __shared__ float Hs[8][68];    // [k][m], padded
    __shared__ float Ws[8][113];   // [k][n], padded
    __shared__ int   rowid_s[64];

    const int tid = threadIdx.x;
    if (tid < 64) {
        int m = m0 + tid;
        rowid_s[tid] = (m < cnt) ? rows[m] : -1;
    }
    __syncthreads();

    // H loader: 64 rows x 8 k = 128 float4 (threads 0..127)
    const int h_row = tid >> 1;
    const int h_k   = (tid & 1) * 4;
    const int h_r   = (tid < 128) ? rowid_s[h_row] : -1;

    const int ty = tid >> 4;   // 0..15 -> rows ty*4..ty*4+3
    const int tx = tid & 15;   // 0..15 -> cols tx*7..tx*7+6

    float acc[4][7];
    #pragma unroll
    for (int i = 0; i < 4; i++)
        #pragma unroll
        for (int j = 0; j < 7; j++) acc[i][j] = 0.f;

    for (int k0 = 0; k0 < HIDDEN; k0 += 8) {
        if (tid < 128) {
            float4 hv = make_float4(0.f, 0.f, 0.f, 0.f);
            if (h_r >= 0)
                hv = *reinterpret_cast<const float4*>(
                    &g_h[(size_t)h_r * HIDDEN + k0 + h_k]);
            Hs[h_k + 0][h_row] = hv.x;
            Hs[h_k + 1][h_row] = hv.y;
            Hs[h_k + 2][h_row] = hv.z;
            Hs[h_k + 3][h_row] = hv.w;
        }
        // W loader: 8 k x 112 n = 896 scalars
        for (int idx = tid; idx < 8 * 112; idx += 256) {
            int kk = idx / 112;
            int nn = idx % 112;
            Ws[kk][nn] = (nn < N_CLASSES)
                       ? W[(size_t)(k0 + kk) * N_CLASSES + nn] : 0.f;
        }
        __syncthreads();

        #pragma unroll
        for (int k = 0; k < 8; k++) {
            float4 av = *reinterpret_cast<const float4*>(&Hs[k][ty * 4]);
            float a[4] = {av.x, av.y, av.z, av.w};
            float b[7];
            #pragma unroll
            for (int j = 0; j < 7; j++) b[j] = Ws[k][tx * 7 + j];
            #pragma unroll
            for (int i = 0; i < 4; i++)
                #pragma unroll
                for (int j = 0; j < 7; j++)
                    acc[i][j] = fmaf(a[i], b[j], acc[i][j]);
        }
        __syncthreads();
    }

    // epilogue: bias + scatter to out
    #pragma unroll
    for (int i = 0; i < 4; i++) {
        int r = rowid_s[ty * 4 + i];
        if (r < 0) continue;
        #pragma unroll
        for (int j = 0; j < 7; j++) {
            int c = tx * 7 + j;
            if (c < N_CLASSES)
                out[(size_t)r * N_CLASSES + c] = acc[i][j] + b2[t * N_CLASSES + c];
        }
    }
}

// ---------------- launcher ----------------
extern "C" void kernel_launch(void* const* d_in, const int* in_sizes, int n_in,
                              void* d_out, int out_size) {
    (void)in_sizes; (void)n_in; (void)out_size;
    const float* x       = (const float*)d_in[0];
    const int*   task_id = (const int*)  d_in[1];
    const float* W1      = (const float*)d_in[2];
    const float* b1      = (const float*)d_in[3];
    const float* W2      = (const float*)d_in[4];
    const float* b2      = (const float*)d_in[5];
    float*       out     = (float*)d_out;

    zero_counts_kernel<<<1, 32>>>();
    bucket_rows_kernel<<<(BATCH + 255) / 256, 256>>>(task_id);

    dim3 g1(HIDDEN / 128, (BATCH + 127) / 128, N_TASKS);
    layer1_kernel<<<g1, 256>>>(x, W1, b1);

    dim3 g2(1, (BATCH + 63) / 64, N_TASKS);
    layer2_kernel<<<g2, 256>>>(W2, b2, out);
}

// round 2
// speedup vs baseline: 1.5148x; 1.5148x over previous
#include <cuda_runtime.h>
#include <cuda_bf16.h>
#include <cstdint>

#define N_TASKS   8
#define D_MODEL   1024
#define HIDDEN    1024
#define N_CLASSES 100
#define BATCH     8192

// ---------------- device scratch (no allocations allowed) ----------------
__device__ int   g_counts[N_TASKS];
__device__ int   g_rowids[N_TASKS * BATCH];
__device__ float g_h[(size_t)BATCH * HIDDEN];   // 32 MB hidden activations

// ---------------- bucketing ----------------
__global__ void zero_counts_kernel() {
    if (threadIdx.x < N_TASKS) g_counts[threadIdx.x] = 0;
}

__global__ void bucket_rows_kernel(const int* __restrict__ task_id) {
    int b = blockIdx.x * blockDim.x + threadIdx.x;
    if (b < BATCH) {
        int t = task_id[b];
        int pos = atomicAdd(&g_counts[t], 1);
        g_rowids[t * BATCH + pos] = b;
    }
}

// ---------------- bf16 split helpers ----------------
__device__ __forceinline__ void split_bf16(float v, __nv_bfloat16& hi, __nv_bfloat16& lo) {
    hi = __float2bfloat16(v);
    lo = __float2bfloat16(v - __bfloat162float(hi));
}

// mma.sync m16n8k16 bf16, fp32 accumulate
__device__ __forceinline__ void mma_bf16(float* c, const uint32_t* a, const uint32_t* b) {
    asm volatile(
        "mma.sync.aligned.m16n8k16.row.col.f32.bf16.bf16.f32 "
        "{%0,%1,%2,%3}, {%4,%5,%6,%7}, {%8,%9}, {%0,%1,%2,%3};\n"
        : "+f"(c[0]), "+f"(c[1]), "+f"(c[2]), "+f"(c[3])
        : "r"(a[0]), "r"(a[1]), "r"(a[2]), "r"(a[3]), "r"(b[0]), "r"(b[1]));
}

// ---------------- generic grouped GEMM (3-term bf16-split emulation) ------
// D[r, n] = act( A[r, :] @ B[:, n] + bias[n] )   for rows r in this task bucket
// Block tile: BM=128, BN=128, BK=32. 256 threads = 8 warps (2m x 4n),
// warp tile 64x32, each warp 4x4 m16n8k16 tiles per k16.
#define BM 128
#define BN 128
#define BK 32
#define SSTR 34   // smem row stride in bf16 (k-contiguous), conflict-tuned

template<bool RELU>
__global__ __launch_bounds__(256, 1)
void mlp_gemm(const float* __restrict__ Asrc,   // [*, K] ld=K, gathered rows
              const float* __restrict__ Bsrc,   // per task [K, Nreal] ld=Nreal
              const float* __restrict__ bias,   // per task [Nreal]
              float* __restrict__ Dst,          // [*, ldOut] scatter rows
              int K, int Nreal, int strideB_task, int strideBias_task, int ldOut) {
    const int t   = blockIdx.z;
    const int cnt = g_counts[t];
    const int m0  = blockIdx.y * BM;
    if (m0 >= cnt) return;
    const int n0  = blockIdx.x * BN;

    const int* rows     = &g_rowids[t * BATCH];
    const float* B      = Bsrc + (size_t)t * strideB_task;
    const float* biasT  = bias + (size_t)t * strideBias_task;

    __shared__ __nv_bfloat16 sAh[BM * SSTR];
    __shared__ __nv_bfloat16 sAl[BM * SSTR];
    __shared__ __nv_bfloat16 sBh[BN * SSTR];
    __shared__ __nv_bfloat16 sBl[BN * SSTR];
    __shared__ int rowid_s[BM];

    const int tid = threadIdx.x;
    if (tid < BM) {
        int m = m0 + tid;
        rowid_s[tid] = (m < cnt) ? rows[m] : -1;
    }
    __syncthreads();

    // ---- loader precompute ----
    // A units: 128 rows x 8 kchunks(4 floats) = 1024 units, 4 per thread
    const float* aptr[4];
    int a_row[4], a_kc[4];
    #pragma unroll
    for (int i = 0; i < 4; i++) {
        int u = tid + i * 256;
        a_row[i] = u >> 3;
        a_kc[i]  = u & 7;
        int r = rowid_s[a_row[i]];
        aptr[i] = (r >= 0) ? (Asrc + (size_t)r * K + a_kc[i] * 4) : nullptr;
    }
    // B units: 16 kpairs x 64 npairs = 1024 units, 4 per thread
    int b_kp[4], b_np[4];
    #pragma unroll
    for (int i = 0; i < 4; i++) {
        int u = tid + i * 256;
        b_kp[i] = u >> 6;
        b_np[i] = u & 63;
    }

    const int warp = tid >> 5;
    const int lane = tid & 31;
    const int wm = warp >> 2;           // 0..1
    const int wn = warp & 3;            // 0..3
    const int g  = lane >> 2;           // group
    const int tg = lane & 3;            // thread-in-group

    float acc[4][4][4];
    #pragma unroll
    for (int i = 0; i < 4; i++)
        #pragma unroll
        for (int j = 0; j < 4; j++)
            #pragma unroll
            for (int q = 0; q < 4; q++) acc[i][j][q] = 0.f;

    // staging registers for global->smem double buffering
    float4 stA[4];
    float2 stB0[4], stB1[4];

    // prologue loads (k block 0)
    #pragma unroll
    for (int i = 0; i < 4; i++) {
        stA[i] = aptr[i] ? *reinterpret_cast<const float4*>(aptr[i])
                         : make_float4(0.f, 0.f, 0.f, 0.f);
        int kk = 2 * b_kp[i];
        int nn = n0 + 2 * b_np[i];
        if (nn < Nreal) {
            stB0[i] = *reinterpret_cast<const float2*>(&B[(size_t)kk * Nreal + nn]);
            stB1[i] = *reinterpret_cast<const float2*>(&B[(size_t)(kk + 1) * Nreal + nn]);
        } else {
            stB0[i] = make_float2(0.f, 0.f);
            stB1[i] = make_float2(0.f, 0.f);
        }
    }

    const int KB = K / BK;
    for (int kb = 0; kb < KB; kb++) {
        // ---- convert + store staged tile to smem ----
        #pragma unroll
        for (int i = 0; i < 4; i++) {
            __nv_bfloat16 h0, l0, h1, l1, h2, l2, h3, l3;
            split_bf16(stA[i].x, h0, l0);
            split_bf16(stA[i].y, h1, l1);
            split_bf16(stA[i].z, h2, l2);
            split_bf16(stA[i].w, h3, l3);
            int base = a_row[i] * SSTR + a_kc[i] * 4;
            *reinterpret_cast<__nv_bfloat162*>(&sAh[base])     = __nv_bfloat162(h0, h1);
            *reinterpret_cast<__nv_bfloat162*>(&sAh[base + 2]) = __nv_bfloat162(h2, h3);
            *reinterpret_cast<__nv_bfloat162*>(&sAl[base])     = __nv_bfloat162(l0, l1);
            *reinterpret_cast<__nv_bfloat162*>(&sAl[base + 2]) = __nv_bfloat162(l2, l3);

            __nv_bfloat16 bh00, bl00, bh01, bl01, bh10, bl10, bh11, bl11;
            split_bf16(stB0[i].x, bh00, bl00);  // (k  , n  )
            split_bf16(stB0[i].y, bh01, bl01);  // (k  , n+1)
            split_bf16(stB1[i].x, bh10, bl10);  // (k+1, n  )
            split_bf16(stB1[i].y, bh11, bl11);  // (k+1, n+1)
            int r0 = (2 * b_np[i]) * SSTR + 2 * b_kp[i];
            int r1 = (2 * b_np[i] + 1) * SSTR + 2 * b_kp[i];
            *reinterpret_cast<__nv_bfloat162*>(&sBh[r0]) = __nv_bfloat162(bh00, bh10);
            *reinterpret_cast<__nv_bfloat162*>(&sBh[r1]) = __nv_bfloat162(bh01, bh11);
            *reinterpret_cast<__nv_bfloat162*>(&sBl[r0]) = __nv_bfloat162(bl00, bl10);
            *reinterpret_cast<__nv_bfloat162*>(&sBl[r1]) = __nv_bfloat162(bl01, bl11);
        }
        __syncthreads();

        // ---- prefetch next k block into registers ----
        if (kb + 1 < KB) {
            int k0 = (kb + 1) * BK;
            #pragma unroll
            for (int i = 0; i < 4; i++) {
                stA[i] = aptr[i] ? *reinterpret_cast<const float4*>(aptr[i] + k0)
                                 : make_float4(0.f, 0.f, 0.f, 0.f);
                int kk = k0 + 2 * b_kp[i];
                int nn = n0 + 2 * b_np[i];
                if (nn < Nreal) {
                    stB0[i] = *reinterpret_cast<const float2*>(&B[(size_t)kk * Nreal + nn]);
                    stB1[i] = *reinterpret_cast<const float2*>(&B[(size_t)(kk + 1) * Nreal + nn]);
                } else {
                    stB0[i] = make_float2(0.f, 0.f);
                    stB1[i] = make_float2(0.f, 0.f);
                }
            }
        }

        // ---- compute on smem tile ----
        #pragma unroll
        for (int kk = 0; kk < BK; kk += 16) {
            uint32_t ah[4][4], al[4][4], bh[4][2], bl[4][2];
            #pragma unroll
            for (int i = 0; i < 4; i++) {
                int mr = (wm * 64 + i * 16 + g) * SSTR + kk + 2 * tg;
                int mr8 = mr + 8 * SSTR;
                ah[i][0] = *reinterpret_cast<const uint32_t*>(&sAh[mr]);
                ah[i][1] = *reinterpret_cast<const uint32_t*>(&sAh[mr8]);
                ah[i][2] = *reinterpret_cast<const uint32_t*>(&sAh[mr + 8]);
                ah[i][3] = *reinterpret_cast<const uint32_t*>(&sAh[mr8 + 8]);
                al[i][0] = *reinterpret_cast<const uint32_t*>(&sAl[mr]);
                al[i][1] = *reinterpret_cast<const uint32_t*>(&sAl[mr8]);
                al[i][2] = *reinterpret_cast<const uint32_t*>(&sAl[mr + 8]);
                al[i][3] = *reinterpret_cast<const uint32_t*>(&sAl[mr8 + 8]);
            }
            #pragma unroll
            for (int j = 0; j < 4; j++) {
                int nr = (wn * 32 + j * 8 + g) * SSTR + kk + 2 * tg;
                bh[j][0] = *reinterpret_cast<const uint32_t*>(&sBh[nr]);
                bh[j][1] = *reinterpret_cast<const uint32_t*>(&sBh[nr + 8]);
                bl[j][0] = *reinterpret_cast<const uint32_t*>(&sBl[nr]);
                bl[j][1] = *reinterpret_cast<const uint32_t*>(&sBl[nr + 8]);
            }
            #pragma unroll
            for (int i = 0; i < 4; i++)
                #pragma unroll
                for (int j = 0; j < 4; j++) {
                    mma_bf16(acc[i][j], ah[i], bh[j]);
                    mma_bf16(acc[i][j], ah[i], bl[j]);
                    mma_bf16(acc[i][j], al[i], bh[j]);
                }
        }
        __syncthreads();
    }

    // ---- epilogue: bias (+relu), scatter rows ----
    #pragma unroll
    for (int j = 0; j < 4; j++) {
        int c = n0 + wn * 32 + j * 8 + 2 * tg;
        if (c >= Nreal) continue;
        float bc0 = biasT[c];
        float bc1 = biasT[c + 1];
        #pragma unroll
        for (int i = 0; i < 4; i++) {
            int lr = wm * 64 + i * 16 + g;
            int r0 = rowid_s[lr];
            int r1 = rowid_s[lr + 8];
            if (r0 >= 0) {
                float v0 = acc[i][j][0] + bc0;
                float v1 = acc[i][j][1] + bc1;
                if (RELU) { v0 = v0 > 0.f ? v0 : 0.f; v1 = v1 > 0.f ? v1 : 0.f; }
                *reinterpret_cast<float2*>(&Dst[(size_t)r0 * ldOut + c]) = make_float2(v0, v1);
            }
            if (r1 >= 0) {
                float v0 = acc[i][j][2] + bc0;
                float v1 = acc[i][j][3] + bc1;
                if (RELU) { v0 = v0 > 0.f ? v0 : 0.f; v1 = v1 > 0.f ? v1 : 0.f; }
                *reinterpret_cast<float2*>(&Dst[(size_t)r1 * ldOut + c]) = make_float2(v0, v1);
            }
        }
    }
}

// ---------------- launcher ----------------
extern "C" void kernel_launch(void* const* d_in, const int* in_sizes, int n_in,
                              void* d_out, int out_size) {
    (void)in_sizes; (void)n_in; (void)out_size;
    const float* x       = (const float*)d_in[0];
    const int*   task_id = (const int*)  d_in[1];
    const float* W1      = (const float*)d_in[2];
    const float* b1      = (const float*)d_in[3];
    const float* W2      = (const float*)d_in[4];
    const float* b2      = (const float*)d_in[5];
    float*       out     = (float*)d_out;

    zero_counts_kernel<<<1, 32>>>();
    bucket_rows_kernel<<<(BATCH + 255) / 256, 256>>>(task_id);

    // layer 1: h = relu(x @ W1[t] + b1[t])  -> g_h (fp32)
    dim3 g1(HIDDEN / BN, BATCH / BM, N_TASKS);
    mlp_gemm<true><<<g1, 256>>>(x, W1, b1, g_h,
                                D_MODEL, HIDDEN,
                                D_MODEL * HIDDEN, HIDDEN, HIDDEN);

    // layer 2: out = h @ W2[t] + b2[t]   (N=100 fits one 128-wide tile)
    dim3 g2(1, BATCH / BM, N_TASKS);
    mlp_gemm<false><<<g2, 256>>>(g_h, W2, b2, out,
                                 HIDDEN, N_CLASSES,
                                 HIDDEN * N_CLASSES, N_CLASSES, N_CLASSES);
}

// round 3
// speedup vs baseline: 3.4641x; 2.2868x over previous
#include <cuda_runtime.h>
#include <cuda_bf16.h>
#include <cstdint>

#define N_TASKS   8
#define D_MODEL   1024
#define HIDDEN    1024
#define N_CLASSES 100
#define BATCH     8192

#define BM 128
#define BN 128
#define BK 32
#define ASTR 40          // A smem row stride (bf16 elems), 80B: 16B-aligned, ldmatrix conflict-free
#define BSTR 136         // B smem row stride (bf16 elems), 272B: 16B-aligned, ldmatrix.trans conflict-free
#define A_ELEMS (BM * ASTR)                 // 5120
#define B_ELEMS (BK * BSTR)                 // 4352
#define STAGE_ELEMS (2 * A_ELEMS + 2 * B_ELEMS)  // 18944
#define SMEM_BYTES  (2 * STAGE_ELEMS * 2)        // 75776 bytes

// ---------------- device scratch ----------------
__device__ int            g_counts[N_TASKS];
__device__ int            g_rowids[N_TASKS * BATCH];
__device__ __nv_bfloat16  g_xh[BATCH * D_MODEL];
__device__ __nv_bfloat16  g_xl[BATCH * D_MODEL];
__device__ __nv_bfloat16  g_w1h[N_TASKS * D_MODEL * HIDDEN];
__device__ __nv_bfloat16  g_w1l[N_TASKS * D_MODEL * HIDDEN];
__device__ __nv_bfloat16  g_w2h[N_TASKS * HIDDEN * 128];
__device__ __nv_bfloat16  g_w2l[N_TASKS * HIDDEN * 128];
__device__ __nv_bfloat16  g_hh[BATCH * HIDDEN];
__device__ __nv_bfloat16  g_hl[BATCH * HIDDEN];
__device__ float          g_part[4 * BATCH * 128];

// ---------------- small helpers ----------------
__device__ __forceinline__ uint32_t s2u(const void* p) {
    return (uint32_t)__cvta_generic_to_shared(p);
}

__device__ __forceinline__ void cp16(__nv_bfloat16* dst, const __nv_bfloat16* src, bool v) {
    uint32_t d = s2u(dst);
    int sz = v ? 16 : 0;
    asm volatile("cp.async.cg.shared.global [%0], [%1], 16, %2;\n"
                 :: "r"(d), "l"(src), "r"(sz));
}
#define CP_COMMIT asm volatile("cp.async.commit_group;\n" ::: "memory")
#define CP_WAIT1  asm volatile("cp.async.wait_group 1;\n" ::: "memory")
#define CP_WAIT0  asm volatile("cp.async.wait_group 0;\n" ::: "memory")

__device__ __forceinline__ void ldsm4(uint32_t* r, uint32_t addr) {
    asm volatile("ldmatrix.sync.aligned.m8n8.x4.shared.b16 {%0,%1,%2,%3}, [%4];"
                 : "=r"(r[0]), "=r"(r[1]), "=r"(r[2]), "=r"(r[3]) : "r"(addr));
}
__device__ __forceinline__ void ldsm2t(uint32_t* r, uint32_t addr) {
    asm volatile("ldmatrix.sync.aligned.m8n8.x2.trans.shared.b16 {%0,%1}, [%2];"
                 : "=r"(r[0]), "=r"(r[1]) : "r"(addr));
}
__device__ __forceinline__ void mma_bf16(float* c, const uint32_t* a, const uint32_t* b) {
    asm volatile(
        "mma.sync.aligned.m16n8k16.row.col.f32.bf16.bf16.f32 "
        "{%0,%1,%2,%3}, {%4,%5,%6,%7}, {%8,%9}, {%0,%1,%2,%3};\n"
        : "+f"(c[0]), "+f"(c[1]), "+f"(c[2]), "+f"(c[3])
        : "r"(a[0]), "r"(a[1]), "r"(a[2]), "r"(a[3]), "r"(b[0]), "r"(b[1]));
}

// ---------------- bucketing ----------------
__global__ void zero_counts_kernel() {
    if (threadIdx.x < N_TASKS) g_counts[threadIdx.x] = 0;
}
__global__ void bucket_rows_kernel(const int* __restrict__ task_id) {
    int b = blockIdx.x * blockDim.x + threadIdx.x;
    if (b < BATCH) {
        int t = task_id[b];
        int pos = atomicAdd(&g_counts[t], 1);
        g_rowids[t * BATCH + pos] = b;
    }
}

// ---------------- fp32 -> bf16 hi/lo split (elementwise, 8/thread) -------
__global__ void split_kernel(const float* __restrict__ src,
                             __nv_bfloat16* __restrict__ dh,
                             __nv_bfloat16* __restrict__ dl, int n8) {
    int i = blockIdx.x * blockDim.x + threadIdx.x;
    if (i >= n8) return;
    float4 v0 = ((const float4*)src)[2 * i];
    float4 v1 = ((const float4*)src)[2 * i + 1];
    float v[8] = {v0.x, v0.y, v0.z, v0.w, v1.x, v1.y, v1.z, v1.w};
    alignas(16) __nv_bfloat16 h[8];
    alignas(16) __nv_bfloat16 l[8];
    #pragma unroll
    for (int k = 0; k < 8; k++) {
        __nv_bfloat16 hb = __float2bfloat16(v[k]);
        h[k] = hb;
        l[k] = __float2bfloat16(v[k] - __bfloat162float(hb));
    }
    ((uint4*)dh)[i] = *(uint4*)h;
    ((uint4*)dl)[i] = *(uint4*)l;
}

// W2 [T*H][100] -> padded [T*H][128] hi/lo bf16 (zero pad)
__global__ void split_w2_kernel(const float* __restrict__ W2,
                                __nv_bfloat16* __restrict__ dh,
                                __nv_bfloat16* __restrict__ dl) {
    int i = blockIdx.x * blockDim.x + threadIdx.x;      // (T*H) * 32
    if (i >= N_TASKS * HIDDEN * 32) return;
    int row = i >> 5, q = i & 31, c = q * 4;
    float v[4] = {0.f, 0.f, 0.f, 0.f};
    if (c < N_CLASSES) {
        float4 t = *(const float4*)(W2 + (size_t)row * N_CLASSES + c);
        v[0] = t.x; v[1] = t.y; v[2] = t.z; v[3] = t.w;
    }
    alignas(8) __nv_bfloat16 h[4];
    alignas(8) __nv_bfloat16 l[4];
    #pragma unroll
    for (int k = 0; k < 4; k++) {
        __nv_bfloat16 hb = __float2bfloat16(v[k]);
        h[k] = hb;
        l[k] = __float2bfloat16(v[k] - __bfloat162float(hb));
    }
    ((uint2*)(dh + (size_t)row * 128))[q] = *(uint2*)h;
    ((uint2*)(dl + (size_t)row * 128))[q] = *(uint2*)l;
}

// ---------------- grouped GEMM, 3-term bf16 split, cp.async + ldmatrix ----
// MODE 0: layer1 — full N sweep (blockIdx.x = n-tile), bias+relu, split-bf16 out to g_hh/g_hl
// MODE 1: layer2 — split-K (blockIdx.x = k-chunk of 4), fp32 partial out to g_part
template<int MODE>
__global__ __launch_bounds__(256, 2)
void gemm_kernel(const __nv_bfloat16* __restrict__ Ah,
                 const __nv_bfloat16* __restrict__ Al,
                 const __nv_bfloat16* __restrict__ Bh_,
                 const __nv_bfloat16* __restrict__ Bl_,
                 const float* __restrict__ bias,
                 int K, int ldB, int strideB_task) {
    const int t   = blockIdx.z;
    const int cnt = g_counts[t];
    const int m0  = blockIdx.y * BM;
    if (m0 >= cnt) return;

    int n0, k0, KB;
    if (MODE == 0) { n0 = blockIdx.x * BN; k0 = 0;                    KB = K / BK; }
    else           { n0 = 0;               k0 = blockIdx.x * (K / 4); KB = K / (4 * BK); }

    const __nv_bfloat16* Bh = Bh_ + (size_t)t * strideB_task;
    const __nv_bfloat16* Bl = Bl_ + (size_t)t * strideB_task;

    extern __shared__ __nv_bfloat16 sm_dyn[];
    __shared__ int rowid_s[BM];

    const int tid  = threadIdx.x;
    const int* rows = &g_rowids[t * BATCH];
    if (tid < BM) {
        int m = m0 + tid;
        rowid_s[tid] = (m < cnt) ? rows[m] : -1;
    }
    __syncthreads();

    // ---- per-thread loader state ----
    // A: 512 16B-chunks per array (128 rows x 4 chunks); ids tid, tid+256
    const int arow0 = tid >> 2,          ak0 = (tid & 3) * 8;
    const int arow1 = (tid + 256) >> 2,  ak1 = ((tid + 256) & 3) * 8;
    const int r0i = rowid_s[arow0], r1i = rowid_s[arow1];
    const bool av0 = (r0i >= 0), av1 = (r1i >= 0);
    const __nv_bfloat16* aph0 = Ah + (size_t)(av0 ? r0i : 0) * K + k0 + ak0;
    const __nv_bfloat16* aph1 = Ah + (size_t)(av1 ? r1i : 0) * K + k0 + ak1;
    const __nv_bfloat16* apl0 = Al + (size_t)(av0 ? r0i : 0) * K + k0 + ak0;
    const __nv_bfloat16* apl1 = Al + (size_t)(av1 ? r1i : 0) * K + k0 + ak1;
    const int aoff0 = arow0 * ASTR + ak0;
    const int aoff1 = arow1 * ASTR + ak1;

    // B: 512 16B-chunks per array (32 k-rows x 16 chunks); ids tid, tid+256
    const int bkr0 = tid >> 4,          bnc0 = (tid & 15) * 8;
    const int bkr1 = (tid + 256) >> 4,  bnc1 = ((tid + 256) & 15) * 8;
    const __nv_bfloat16* bph0 = Bh + (size_t)(k0 + bkr0) * ldB + n0 + bnc0;
    const __nv_bfloat16* bph1 = Bh + (size_t)(k0 + bkr1) * ldB + n0 + bnc1;
    const __nv_bfloat16* bpl0 = Bl + (size_t)(k0 + bkr0) * ldB + n0 + bnc0;
    const __nv_bfloat16* bpl1 = Bl + (size_t)(k0 + bkr1) * ldB + n0 + bnc1;
    const int boff0 = bkr0 * BSTR + bnc0;
    const int boff1 = bkr1 * BSTR + bnc1;

    // ---- compute-side lane mapping ----
    const int warp = tid >> 5, lane = tid & 31;
    const int wm = warp >> 2;           // 0..1 (m)
    const int wn = warp & 3;            // 0..3 (n)
    const int g  = lane >> 2, tg = lane & 3;
    const uint32_t a_lane = (uint32_t)((wm * 64 + (lane & 7) + ((lane >> 3) & 1) * 8) * ASTR
                                       + (lane >> 4) * 8);
    const uint32_t b_lane = (uint32_t)((((lane & 15) >> 3) * 8 + (lane & 7)) * BSTR + wn * 32);

    float acc[4][4][4];
    #pragma unroll
    for (int i = 0; i < 4; i++)
        #pragma unroll
        for (int j = 0; j < 4; j++)
            #pragma unroll
            for (int q = 0; q < 4; q++) acc[i][j][q] = 0.f;

    auto issue_stage = [&](int s, int kc) {
        __nv_bfloat16* base = sm_dyn + s * STAGE_ELEMS;
        cp16(base + aoff0, aph0 + kc, av0);
        cp16(base + aoff1, aph1 + kc, av1);
        cp16(base + A_ELEMS + aoff0, apl0 + kc, av0);
        cp16(base + A_ELEMS + aoff1, apl1 + kc, av1);
        const size_t bk = (size_t)kc * ldB;
        cp16(base + 2 * A_ELEMS + boff0, bph0 + bk, true);
        cp16(base + 2 * A_ELEMS + boff1, bph1 + bk, true);
        cp16(base + 2 * A_ELEMS + B_ELEMS + boff0, bpl0 + bk, true);
        cp16(base + 2 * A_ELEMS + B_ELEMS + boff1, bpl1 + bk, true);
    };

    auto compute_stage = [&](int s) {
        const __nv_bfloat16* base = sm_dyn + s * STAGE_ELEMS;
        const uint32_t uA_h = s2u(base);
        const uint32_t uA_l = uA_h + A_ELEMS * 2;
        const uint32_t uB_h = uA_l + A_ELEMS * 2;
        const uint32_t uB_l = uB_h + B_ELEMS * 2;
        #pragma unroll
        for (int kk = 0; kk < BK; kk += 16) {
            uint32_t bhf[4][2], blf[4][2];
            #pragma unroll
            for (int j = 0; j < 4; j++) {
                uint32_t off = 2u * (b_lane + kk * BSTR + j * 8);
                ldsm2t(bhf[j], uB_h + off);
                ldsm2t(blf[j], uB_l + off);
            }
            #pragma unroll
            for (int i = 0; i < 4; i++) {
                uint32_t ah[4], al[4];
                uint32_t off = 2u * (a_lane + i * 16 * ASTR + kk);
                ldsm4(ah, uA_h + off);
                ldsm4(al, uA_l + off);
                #pragma unroll
                for (int j = 0; j < 4; j++) {
                    mma_bf16(acc[i][j], ah, bhf[j]);
                    mma_bf16(acc[i][j], ah, blf[j]);
                    mma_bf16(acc[i][j], al, bhf[j]);
                }
            }
        }
    };

    issue_stage(0, 0);
    CP_COMMIT;
    for (int kb = 0; kb < KB; ++kb) {
        if (kb + 1 < KB) { issue_stage((kb + 1) & 1, (kb + 1) * BK); CP_COMMIT; CP_WAIT1; }
        else             { CP_WAIT0; }
        __syncthreads();
        compute_stage(kb & 1);
        __syncthreads();
    }

    // ---- epilogue ----
    if (MODE == 0) {
        const float* biasT = bias + (size_t)t * HIDDEN;
        #pragma unroll
        for (int j = 0; j < 4; j++) {
            int c = n0 + wn * 32 + j * 8 + 2 * tg;
            float bc0 = biasT[c], bc1 = biasT[c + 1];
            #pragma unroll
            for (int i = 0; i < 4; i++) {
                int lr = wm * 64 + i * 16 + g;
                int rr0 = rowid_s[lr], rr1 = rowid_s[lr + 8];
                if (rr0 >= 0) {
                    float v0 = acc[i][j][0] + bc0; v0 = v0 > 0.f ? v0 : 0.f;
                    float v1 = acc[i][j][1] + bc1; v1 = v1 > 0.f ? v1 : 0.f;
                    __nv_bfloat16 h0 = __float2bfloat16(v0), h1 = __float2bfloat16(v1);
                    __nv_bfloat16 l0 = __float2bfloat16(v0 - __bfloat162float(h0));
                    __nv_bfloat16 l1 = __float2bfloat16(v1 - __bfloat162float(h1));
                    *(__nv_bfloat162*)&g_hh[(size_t)rr0 * HIDDEN + c] = __nv_bfloat162(h0, h1);
                    *(__nv_bfloat162*)&g_hl[(size_t)rr0 * HIDDEN + c] = __nv_bfloat162(l0, l1);
                }
                if (rr1 >= 0) {
                    float v0 = acc[i][j][2] + bc0; v0 = v0 > 0.f ? v0 : 0.f;
                    float v1 = acc[i][j][3] + bc1; v1 = v1 > 0.f ? v1 : 0.f;
                    __nv_bfloat16 h0 = __float2bfloat16(v0), h1 = __float2bfloat16(v1);
                    __nv_bfloat16 l0 = __float2bfloat16(v0 - __bfloat162float(h0));
                    __nv_bfloat16 l1 = __float2bfloat16(v1 - __bfloat162float(h1));
                    *(__nv_bfloat162*)&g_hh[(size_t)rr1 * HIDDEN + c] = __nv_bfloat162(h0, h1);
                    *(__nv_bfloat162*)&g_hl[(size_t)rr1 * HIDDEN + c] = __nv_bfloat162(l0, l1);
                }
            }
        }
    } else {
        float* P = g_part + (size_t)blockIdx.x * BATCH * 128;
        #pragma unroll
        for (int j = 0; j < 4; j++) {
            int c = wn * 32 + j * 8 + 2 * tg;
            #pragma unroll
            for (int i = 0; i < 4; i++) {
                int lr = wm * 64 + i * 16 + g;
                int rr0 = rowid_s[lr], rr1 = rowid_s[lr + 8];
                if (rr0 >= 0)
                    *(float2*)(P + (size_t)rr0 * 128 + c) = make_float2(acc[i][j][0], acc[i][j][1]);
                if (rr1 >= 0)
                    *(float2*)(P + (size_t)rr1 * 128 + c) = make_float2(acc[i][j][2], acc[i][j][3]);
            }
        }
    }
}

// ---------------- split-K reduce + bias for layer2 ----------------
__global__ void reduce_kernel(const int* __restrict__ task_id,
                              const float* __restrict__ b2,
                              float* __restrict__ out) {
    int i = blockIdx.x * blockDim.x + threadIdx.x;   // BATCH * 25
    if (i >= BATCH * 25) return;
    int r = i / 25, q = i % 25, c = q * 4;
    int t = task_id[r];
    float4 s0 = *(const float4*)(g_part + ((size_t)0 * BATCH + r) * 128 + c);
    float4 s1 = *(const float4*)(g_part + ((size_t)1 * BATCH + r) * 128 + c);
    float4 s2 = *(const float4*)(g_part + ((size_t)2 * BATCH + r) * 128 + c);
    float4 s3 = *(const float4*)(g_part + ((size_t)3 * BATCH + r) * 128 + c);
    float4 b  = *(const float4*)(b2 + (size_t)t * N_CLASSES + c);
    float4 o;
    o.x = s0.x + s1.x + s2.x + s3.x + b.x;
    o.y = s0.y + s1.y + s2.y + s3.y + b.y;
    o.z = s0.z + s1.z + s2.z + s3.z + b.z;
    o.w = s0.w + s1.w + s2.w + s3.w + b.w;
    *(float4*)(out + (size_t)r * N_CLASSES + c) = o;
}

// ---------------- launcher ----------------
extern "C" void kernel_launch(void* const* d_in, const int* in_sizes, int n_in,
                              void* d_out, int out_size) {
    (void)in_sizes; (void)n_in; (void)out_size;
    const float* x       = (const float*)d_in[0];
    const int*   task_id = (const int*)  d_in[1];
    const float* W1      = (const float*)d_in[2];
    const float* b1      = (const float*)d_in[3];
    const float* W2      = (const float*)d_in[4];
    const float* b2      = (const float*)d_in[5];
    float*       out     = (float*)d_out;

    static __nv_bfloat16 *p_xh = nullptr, *p_xl, *p_w1h, *p_w1l, *p_w2h, *p_w2l, *p_hh, *p_hl;
    // resolve device-symbol addresses (host-side, cheap, deterministic)
    if (!p_xh) {
        cudaGetSymbolAddress((void**)&p_xh,  g_xh);
        cudaGetSymbolAddress((void**)&p_xl,  g_xl);
        cudaGetSymbolAddress((void**)&p_w1h, g_w1h);
        cudaGetSymbolAddress((void**)&p_w1l, g_w1l);
        cudaGetSymbolAddress((void**)&p_w2h, g_w2h);
        cudaGetSymbolAddress((void**)&p_w2l, g_w2l);
        cudaGetSymbolAddress((void**)&p_hh,  g_hh);
        cudaGetSymbolAddress((void**)&p_hl,  g_hl);
    }

    cudaFuncSetAttribute(gemm_kernel<0>, cudaFuncAttributeMaxDynamicSharedMemorySize, SMEM_BYTES);
    cudaFuncSetAttribute(gemm_kernel<1>, cudaFuncAttributeMaxDynamicSharedMemorySize, SMEM_BYTES);

    zero_counts_kernel<<<1, 32>>>();
    bucket_rows_kernel<<<(BATCH + 255) / 256, 256>>>(task_id);

    // splits
    const int n8x = BATCH * D_MODEL / 8;            // 1048576
    split_kernel<<<(n8x + 255) / 256, 256>>>(x,  p_xh,  p_xl,  n8x);
    const int n8w = N_TASKS * D_MODEL * HIDDEN / 8; // 1048576
    split_kernel<<<(n8w + 255) / 256, 256>>>(W1, p_w1h, p_w1l, n8w);
    split_w2_kernel<<<(N_TASKS * HIDDEN * 32 + 255) / 256, 256>>>(W2, p_w2h, p_w2l);

    // layer 1: h = relu(x @ W1[t] + b1[t]) -> bf16 hi/lo
    dim3 g1(HIDDEN / BN, BATCH / BM, N_TASKS);
    gemm_kernel<0><<<g1, 256, SMEM_BYTES>>>(p_xh, p_xl, p_w1h, p_w1l, b1,
                                            D_MODEL, HIDDEN, D_MODEL * HIDDEN);

    // layer 2: split-K=4 partials
    dim3 g2(4, BATCH / BM, N_TASKS);
    gemm_kernel<1><<<g2, 256, SMEM_BYTES>>>(p_hh, p_hl, p_w2h, p_w2l, nullptr,
                                            HIDDEN, 128, HIDDEN * 128);

    // reduce + bias -> out
    reduce_kernel<<<(BATCH * 25 + 255) / 256, 256>>>(task_id, b2, out);
}